// round 1
// baseline (speedup 1.0000x reference)
#include <cuda_runtime.h>

#define S_LEN 8192
#define EDIM  64
#define BM    64
#define BN    64
#define NBLK  (S_LEN / BM)   // 128 row-block CTAs
#define PAD   68             // smem row pad (float4-aligned, de-conflicted)
#define CONV_BLOCKS 128
#define CONV_W2 (S_LEN - 1)  // 8191
#define CONV_H2 (EDIM - 1)   // 63

// ---------------- device scratch (no runtime allocation allowed) ----------------
__device__ float g_q[S_LEN * EDIM];
__device__ float g_k[S_LEN * EDIM];
__device__ float g_v[S_LEN * EDIM];
__device__ float g_pool[NBLK][EDIM];   // per-CTA partial column sums of attn_out/l
__device__ float g_sig[CONV_BLOCKS];   // per-block partial sigmoid sums

// ---------------- kernel 1: fused Q/K/V projection ----------------
// y = x @ W + b, x:(8192,64) W:(64,64). gridDim = (256, 3), block = 256.
__global__ void proj_kernel(const float* __restrict__ x,
                            const float* __restrict__ Wq, const float* __restrict__ bq,
                            const float* __restrict__ Wk, const float* __restrict__ bk,
                            const float* __restrict__ Wv, const float* __restrict__ bv) {
    __shared__ float xs[32][EDIM];
    __shared__ float Ws[EDIM][EDIM];
    __shared__ float bs[EDIM];

    const int which = blockIdx.y;
    const float* W = (which == 0) ? Wq : (which == 1) ? Wk : Wv;
    const float* b = (which == 0) ? bq : (which == 1) ? bk : bv;
    float* dst = (which == 0) ? g_q : (which == 1) ? g_k : g_v;

    const int r0  = blockIdx.x * 32;
    const int tid = threadIdx.x;

    for (int i = tid; i < 32 * EDIM; i += 256)
        xs[i >> 6][i & 63] = x[(r0 + (i >> 6)) * EDIM + (i & 63)];
    for (int i = tid; i < EDIM * EDIM; i += 256)
        Ws[i >> 6][i & 63] = W[i];
    if (tid < EDIM) bs[tid] = b[tid];
    __syncthreads();

    const int e  = tid & 63;
    const int rg = tid >> 6;     // 0..3
    float acc[8];
#pragma unroll
    for (int k = 0; k < 8; k++) acc[k] = bs[e];
#pragma unroll 8
    for (int f = 0; f < EDIM; f++) {
        const float w = Ws[f][e];
#pragma unroll
        for (int k = 0; k < 8; k++) acc[k] += xs[rg + 4 * k][f] * w;
    }
#pragma unroll
    for (int k = 0; k < 8; k++)
        dst[(r0 + rg + 4 * k) * EDIM + e] = acc[k];
}

// ---------------- kernel 2: conv 2x2 + sigmoid partial sum ----------------
// logit(i,j) = w00*x[j][i] + w01*x[j+1][i] + w10*x[j][i+1] + w11*x[j+1][i+1] + cb
// over i in [0,63), j in [0,8191); sum of sigmoid(logit).
__global__ void conv_kernel(const float* __restrict__ x,
                            const float* __restrict__ cw,
                            const float* __restrict__ cb) {
    const float w00 = cw[0], w01 = cw[1], w10 = cw[2], w11 = cw[3];
    const float bias = cb[0];
    const int total = CONV_H2 * CONV_W2;

    float acc = 0.f;
    for (int n = blockIdx.x * blockDim.x + threadIdx.x; n < total;
         n += gridDim.x * blockDim.x) {
        const int i = n % CONV_H2;   // over E (coalesced inner)
        const int j = n / CONV_H2;   // over S
        const float z = w00 * x[j * EDIM + i]
                      + w01 * x[(j + 1) * EDIM + i]
                      + w10 * x[j * EDIM + i + 1]
                      + w11 * x[(j + 1) * EDIM + i + 1]
                      + bias;
        acc += 1.f / (1.f + __expf(-z));
    }

    __shared__ float red[256];
    red[threadIdx.x] = acc;
    __syncthreads();
    for (int s2 = 128; s2 > 0; s2 >>= 1) {
        if (threadIdx.x < s2) red[threadIdx.x] += red[threadIdx.x + s2];
        __syncthreads();
    }
    if (threadIdx.x == 0) g_sig[blockIdx.x] = red[0];
}

// ---------------- kernel 3: attention (no-max-rescale flash) ----------------
// One CTA per 64 query rows. Accumulates O_i = sum_t exp(s_it) v_t, l_i = sum_t exp(s_it),
// then reduces sum_i O_i / l_i into g_pool[block].
__global__ void fa_kernel() {
    extern __shared__ float sm[];
    float* Qt   = sm;                 // [E][PAD]  (e-major: Qt[e*PAD + i])
    float* Ks   = Qt + EDIM * PAD;    // [E][PAD]  (e-major: Ks[e*PAD + j])
    float* Vs   = Ks + EDIM * PAD;    // [BN][PAD] (Vs[j*PAD + e])
    float* Ps   = Vs + BN * PAD;      // [BM][PAD] (Ps[i*PAD + j])
    float* pool = Ps + BM * PAD;      // [E]

    const int tid = threadIdx.x;
    const int tx = tid & 15;          // 0..15 (cols)
    const int ty = tid >> 4;          // 0..15 (rows)
    const int i0 = blockIdx.x * BM;

    // Load Q tile transposed (Qt[e][i])
    for (int n = tid; n < BM * EDIM; n += 256) {
        const int i = n >> 6, e = n & 63;
        Qt[e * PAD + i] = g_q[(i0 + i) * EDIM + e];
    }
    if (tid < EDIM) pool[tid] = 0.f;

    float O[4][4] = {};   // rows ty*4+ii, cols tx*4+ee
    float l[4]    = {};

    for (int t0 = 0; t0 < S_LEN; t0 += BN) {
        __syncthreads();  // guard Ks/Vs overwrite (and Qt/pool on first iter)
        for (int n = tid; n < BN * EDIM; n += 256) {
            const int j = n >> 6, e = n & 63;
            const int g = (t0 + j) * EDIM + e;
            Ks[e * PAD + j] = g_k[g];
            Vs[j * PAD + e] = g_v[g];
        }
        __syncthreads();

        // GEMM1: scores = Q K^T
        float acc[4][4] = {};
#pragma unroll 8
        for (int e = 0; e < EDIM; e++) {
            const float4 qv = *(const float4*)&Qt[e * PAD + ty * 4];
            const float4 kv = *(const float4*)&Ks[e * PAD + tx * 4];
            acc[0][0] += qv.x * kv.x; acc[0][1] += qv.x * kv.y;
            acc[0][2] += qv.x * kv.z; acc[0][3] += qv.x * kv.w;
            acc[1][0] += qv.y * kv.x; acc[1][1] += qv.y * kv.y;
            acc[1][2] += qv.y * kv.z; acc[1][3] += qv.y * kv.w;
            acc[2][0] += qv.z * kv.x; acc[2][1] += qv.z * kv.y;
            acc[2][2] += qv.z * kv.z; acc[2][3] += qv.z * kv.w;
            acc[3][0] += qv.w * kv.x; acc[3][1] += qv.w * kv.y;
            acc[3][2] += qv.w * kv.z; acc[3][3] += qv.w * kv.w;
        }

        // exp (scale = E^-0.5 = 0.125; scores are small -> no max needed)
#pragma unroll
        for (int ii = 0; ii < 4; ii++)
#pragma unroll
            for (int jj = 0; jj < 4; jj++)
                Ps[(ty * 4 + ii) * PAD + (tx * 4 + jj)] = __expf(acc[ii][jj] * 0.125f);
        __syncthreads();

        // GEMM2: O += P V, l += rowsum(P)
#pragma unroll 8
        for (int j = 0; j < BN; j++) {
            const float p0 = Ps[(ty * 4 + 0) * PAD + j];
            const float p1 = Ps[(ty * 4 + 1) * PAD + j];
            const float p2 = Ps[(ty * 4 + 2) * PAD + j];
            const float p3 = Ps[(ty * 4 + 3) * PAD + j];
            const float4 vv = *(const float4*)&Vs[j * PAD + tx * 4];
            O[0][0] += p0 * vv.x; O[0][1] += p0 * vv.y; O[0][2] += p0 * vv.z; O[0][3] += p0 * vv.w;
            O[1][0] += p1 * vv.x; O[1][1] += p1 * vv.y; O[1][2] += p1 * vv.z; O[1][3] += p1 * vv.w;
            O[2][0] += p2 * vv.x; O[2][1] += p2 * vv.y; O[2][2] += p2 * vv.z; O[2][3] += p2 * vv.w;
            O[3][0] += p3 * vv.x; O[3][1] += p3 * vv.y; O[3][2] += p3 * vv.z; O[3][3] += p3 * vv.w;
            l[0] += p0; l[1] += p1; l[2] += p2; l[3] += p3;
        }
    }
    __syncthreads();

    // per-row normalize, reduce over the 64 rows of this CTA
    float invl[4];
#pragma unroll
    for (int ii = 0; ii < 4; ii++) invl[ii] = 1.f / l[ii];
#pragma unroll
    for (int ee = 0; ee < 4; ee++) {
        float s = 0.f;
#pragma unroll
        for (int ii = 0; ii < 4; ii++) s += O[ii][ee] * invl[ii];
        atomicAdd(&pool[tx * 4 + ee], s);
    }
    __syncthreads();
    if (tid < EDIM) g_pool[blockIdx.x][tid] = pool[tid];
}

// ---------------- kernel 4: final reduce + output projection ----------------
__global__ void final_kernel(const float* __restrict__ Wp,
                             const float* __restrict__ bp,
                             float* __restrict__ out) {
    __shared__ float ps[EDIM];
    __shared__ float cf;
    const int t = threadIdx.x;  // 64 threads

    if (t == 0) {
        float s = 0.f;
        for (int c = 0; c < CONV_BLOCKS; c++) s += g_sig[c];
        cf = s / (float)(CONV_H2 * CONV_W2);
    }
    float pe = 0.f;
    for (int c = 0; c < NBLK; c++) pe += g_pool[c][t];
    __syncthreads();
    ps[t] = pe * (1.f / (float)S_LEN) * cf;
    __syncthreads();
    if (t < 4) {
        float o = bp[t];
#pragma unroll 8
        for (int e = 0; e < EDIM; e++) o += ps[e] * Wp[e * 4 + t];
        out[t] = o;
    }
}

// ---------------- launcher ----------------
extern "C" void kernel_launch(void* const* d_in, const int* in_sizes, int n_in,
                              void* d_out, int out_size) {
    const float* x      = (const float*)d_in[0];
    const float* conv_w = (const float*)d_in[1];
    const float* conv_b = (const float*)d_in[2];
    const float* Wq     = (const float*)d_in[3];
    const float* bq     = (const float*)d_in[4];
    const float* Wk     = (const float*)d_in[5];
    const float* bk     = (const float*)d_in[6];
    const float* Wv     = (const float*)d_in[7];
    const float* bv     = (const float*)d_in[8];
    const float* Wp     = (const float*)d_in[9];
    const float* bp     = (const float*)d_in[10];
    float* out = (float*)d_out;

    const int fa_smem = (4 * EDIM * PAD + EDIM) * (int)sizeof(float);  // 69888 B
    cudaFuncSetAttribute(fa_kernel, cudaFuncAttributeMaxDynamicSharedMemorySize, fa_smem);

    proj_kernel<<<dim3(S_LEN / 32, 3), 256>>>(x, Wq, bq, Wk, bk, Wv, bv);
    conv_kernel<<<CONV_BLOCKS, 256>>>(x, conv_w, conv_b);
    fa_kernel<<<NBLK, 256, fa_smem>>>();
    final_kernel<<<1, 64>>>(Wp, bp, out);
}

// round 3
// speedup vs baseline: 3.3573x; 3.3573x over previous
#include <cuda_runtime.h>
#include <cuda_bf16.h>
#include <cstdint>

#define S_LEN 8192
#define EDIM  64
#define BM    128
#define BN    128
#define NRB   (S_LEN / BM)      // 64 row blocks
#define NCTA  (NRB * 2)         // 128 CTAs (x2 key halves)
#define KHALF (S_LEN / 2)       // 4096
#define NTILE (KHALF / BN)      // 32 key tiles per CTA
#define CONV_BLOCKS 128
#define CONV_W2 (S_LEN - 1)
#define CONV_H2 (EDIM - 1)

#define ROWB  144               // padded row stride bytes (64 bf16 + 8 pad)
#define TILEB (128 * ROWB)      // 18432 B per tile buffer
#define SMEM_TOTAL (8 * TILEB)  // 147456 B (double-buffered Khi,Klo,Vhi,Vlo)

// ---------------- device scratch ----------------
__device__ __nv_bfloat16 g_qhi[S_LEN * EDIM];
__device__ __nv_bfloat16 g_qlo[S_LEN * EDIM];
__device__ __nv_bfloat16 g_khi[S_LEN * EDIM];
__device__ __nv_bfloat16 g_klo[S_LEN * EDIM];
__device__ __nv_bfloat16 g_vhi[S_LEN * EDIM];
__device__ __nv_bfloat16 g_vlo[S_LEN * EDIM];
__device__ float g_O[NCTA][BM][EDIM];
__device__ float g_l[NCTA][BM];
__device__ float g_pool[NRB][EDIM];
__device__ float g_sig[CONV_BLOCKS];

// ---------------- PTX helpers (generic sm_80+ features only) ----------------
__device__ __forceinline__ uint32_t smem_u32(const void* p) {
    uint32_t a;
    asm("{ .reg .u64 t; cvta.to.shared.u64 t, %1; cvt.u32.u64 %0, t; }" : "=r"(a) : "l"(p));
    return a;
}
__device__ __forceinline__ void cp16(uint32_t dst, const void* src) {
    asm volatile("cp.async.cg.shared.global [%0], [%1], 16;" :: "r"(dst), "l"(src));
}
#define CP_COMMIT() asm volatile("cp.async.commit_group;" ::: "memory")
#define CP_WAIT0()  asm volatile("cp.async.wait_group 0;" ::: "memory")

__device__ __forceinline__ void ldsm4(uint32_t* r, uint32_t a) {
    asm volatile("ldmatrix.sync.aligned.m8n8.x4.shared.b16 {%0,%1,%2,%3}, [%4];"
                 : "=r"(r[0]), "=r"(r[1]), "=r"(r[2]), "=r"(r[3]) : "r"(a));
}
__device__ __forceinline__ void ldsm4t(uint32_t* r, uint32_t a) {
    asm volatile("ldmatrix.sync.aligned.m8n8.x4.trans.shared.b16 {%0,%1,%2,%3}, [%4];"
                 : "=r"(r[0]), "=r"(r[1]), "=r"(r[2]), "=r"(r[3]) : "r"(a));
}
__device__ __forceinline__ void mma_bf16(float* d, const uint32_t* a, const uint32_t* b) {
    asm volatile("mma.sync.aligned.m16n8k16.row.col.f32.bf16.bf16.f32 "
                 "{%0,%1,%2,%3}, {%4,%5,%6,%7}, {%8,%9}, {%0,%1,%2,%3};"
                 : "+f"(d[0]), "+f"(d[1]), "+f"(d[2]), "+f"(d[3])
                 : "r"(a[0]), "r"(a[1]), "r"(a[2]), "r"(a[3]), "r"(b[0]), "r"(b[1]));
}
__device__ __forceinline__ uint32_t pack_bf16x2(float lo, float hi) {
    uint32_t r;
    asm("cvt.rn.satfinite.bf16x2.f32 %0, %1, %2;" : "=r"(r) : "f"(hi), "f"(lo));
    return r;
}

// ---------------- kernel 1: fused Q/K/V projection + bf16 hi/lo split ----------------
__global__ void proj_kernel(const float* __restrict__ x,
                            const float* __restrict__ Wq, const float* __restrict__ bq,
                            const float* __restrict__ Wk, const float* __restrict__ bk,
                            const float* __restrict__ Wv, const float* __restrict__ bv) {
    __shared__ float xs[32][EDIM];
    __shared__ float Ws[EDIM][EDIM];
    __shared__ float bs[EDIM];

    const int which = blockIdx.y;
    const float* W = (which == 0) ? Wq : (which == 1) ? Wk : Wv;
    const float* b = (which == 0) ? bq : (which == 1) ? bk : bv;
    __nv_bfloat16* dhi = (which == 0) ? g_qhi : (which == 1) ? g_khi : g_vhi;
    __nv_bfloat16* dlo = (which == 0) ? g_qlo : (which == 1) ? g_klo : g_vlo;

    const int r0  = blockIdx.x * 32;
    const int tid = threadIdx.x;

    for (int i = tid; i < 32 * EDIM; i += 256)
        xs[i >> 6][i & 63] = x[(r0 + (i >> 6)) * EDIM + (i & 63)];
    for (int i = tid; i < EDIM * EDIM; i += 256)
        Ws[i >> 6][i & 63] = W[i];
    if (tid < EDIM) bs[tid] = b[tid];
    __syncthreads();

    const int e  = tid & 63;
    const int rg = tid >> 6;     // 0..3
    float acc[8];
#pragma unroll
    for (int k = 0; k < 8; k++) acc[k] = bs[e];
#pragma unroll 8
    for (int f = 0; f < EDIM; f++) {
        const float w = Ws[f][e];
#pragma unroll
        for (int k = 0; k < 8; k++) acc[k] += xs[rg + 4 * k][f] * w;
    }
#pragma unroll
    for (int k = 0; k < 8; k++) {
        const int row = r0 + rg + 4 * k;
        __nv_bfloat16 h = __float2bfloat16(acc[k]);
        __nv_bfloat16 l = __float2bfloat16(acc[k] - __bfloat162float(h));
        dhi[row * EDIM + e] = h;
        dlo[row * EDIM + e] = l;
    }
}

// ---------------- kernel 2: conv 2x2 + sigmoid partial sums ----------------
__global__ void conv_kernel(const float* __restrict__ x,
                            const float* __restrict__ cw,
                            const float* __restrict__ cb) {
    const float w00 = cw[0], w01 = cw[1], w10 = cw[2], w11 = cw[3];
    const float bias = cb[0];
    const int total = CONV_H2 * CONV_W2;

    float acc = 0.f;
    for (int n = blockIdx.x * blockDim.x + threadIdx.x; n < total;
         n += gridDim.x * blockDim.x) {
        const int i = n % CONV_H2;
        const int j = n / CONV_H2;
        const float z = w00 * x[j * EDIM + i]
                      + w01 * x[(j + 1) * EDIM + i]
                      + w10 * x[j * EDIM + i + 1]
                      + w11 * x[(j + 1) * EDIM + i + 1]
                      + bias;
        acc += 1.f / (1.f + __expf(-z));
    }

    __shared__ float red[256];
    red[threadIdx.x] = acc;
    __syncthreads();
    for (int s2 = 128; s2 > 0; s2 >>= 1) {
        if (threadIdx.x < s2) red[threadIdx.x] += red[threadIdx.x + s2];
        __syncthreads();
    }
    if (threadIdx.x == 0) g_sig[blockIdx.x] = red[0];
}

// ---------------- async tile loader: 128 rows x 64 bf16, padded rows ----------------
__device__ __forceinline__ void load_part(uint32_t dst, const __nv_bfloat16* __restrict__ src,
                                          int row0, int tid) {
#pragma unroll
    for (int it = 0; it < 4; it++) {
        const int n = tid + it * 256;
        const int j = n >> 3, seg = n & 7;
        cp16(dst + j * ROWB + seg * 16, src + (row0 + j) * EDIM + seg * 8);
    }
}

// ---------------- kernel 3: HMMA flash attention (no-max softmax, split-K) ----------------
__global__ void __launch_bounds__(256, 1) fa_kernel() {
    extern __shared__ char sm[];
    const uint32_t smb = smem_u32(sm);
    const int tid = threadIdx.x;
    const int wid = tid >> 5;
    const int lid = tid & 31;
    const int rb = blockIdx.x >> 1;
    const int kh = blockIdx.x & 1;
    const int i0 = rb * BM;
    const int kbase = kh * KHALF;

    // lane offset patterns for ldmatrix address generation
    const int lr  = (lid & 7) + ((lid >> 3) & 1) * 8;   // A / V(trans) row pattern
    const int lc  = ((lid >> 4) & 1) * 8;               // A / V(trans) col pattern
    const int lr2 = (lid & 7) + ((lid >> 4) & 1) * 8;   // K(B) row pattern
    const int lc2 = ((lid >> 3) & 1) * 8;               // K(B) col pattern

    // ---- stage Q hi/lo through smem, build persistent A-frags ----
#pragma unroll
    for (int it = 0; it < 4; it++) {
        const int n = tid + it * 256;
        const int j = n >> 3, seg = n & 7;
        *(uint4*)(sm + j * ROWB + seg * 16) = *(const uint4*)(g_qhi + (i0 + j) * EDIM + seg * 8);
        *(uint4*)(sm + TILEB + j * ROWB + seg * 16) = *(const uint4*)(g_qlo + (i0 + j) * EDIM + seg * 8);
    }
    __syncthreads();

    uint32_t qh[4][4], ql[4][4];
    {
        const uint32_t addrA = smb + (16 * wid + lr) * ROWB + lc * 2;
#pragma unroll
        for (int kc = 0; kc < 4; kc++) ldsm4(qh[kc], addrA + kc * 32);
#pragma unroll
        for (int kc = 0; kc < 4; kc++) ldsm4(ql[kc], addrA + TILEB + kc * 32);
    }
    __syncthreads();

    // ---- prologue: prefetch tile 0 into buffer 0 ----
    load_part(smb + 0 * TILEB, g_khi, kbase, tid);
    load_part(smb + 1 * TILEB, g_klo, kbase, tid);
    load_part(smb + 2 * TILEB, g_vhi, kbase, tid);
    load_part(smb + 3 * TILEB, g_vlo, kbase, tid);
    CP_COMMIT();

    float Oacc[8][4];
#pragma unroll
    for (int i = 0; i < 8; i++)
#pragma unroll
        for (int j = 0; j < 4; j++) Oacc[i][j] = 0.f;
    float l0 = 0.f, l1 = 0.f;

    for (int t = 0; t < NTILE; t++) {
        CP_WAIT0();
        __syncthreads();

        if (t + 1 < NTILE) {  // prefetch next tile into other buffer
            const uint32_t nb = smb + ((t + 1) & 1) * 4 * TILEB;
            const int k0n = kbase + (t + 1) * BN;
            load_part(nb + 0 * TILEB, g_khi, k0n, tid);
            load_part(nb + 1 * TILEB, g_klo, k0n, tid);
            load_part(nb + 2 * TILEB, g_vhi, k0n, tid);
            load_part(nb + 3 * TILEB, g_vlo, k0n, tid);
            CP_COMMIT();
        }

        const uint32_t cb = smb + (t & 1) * 4 * TILEB;

        // ---- GEMM1: S(16x128 per warp) = Qhi*Khi + Qlo*Khi + Qhi*Klo ----
        float sacc[16][4];
#pragma unroll
        for (int i = 0; i < 16; i++)
#pragma unroll
            for (int j = 0; j < 4; j++) sacc[i][j] = 0.f;

        const uint32_t addrK = cb + lr2 * ROWB + lc2 * 2;
#pragma unroll
        for (int kc = 0; kc < 4; kc++) {
            uint32_t kb[16][2];
#pragma unroll
            for (int p = 0; p < 8; p++) ldsm4(&kb[2 * p][0], addrK + p * (16 * ROWB) + kc * 32);
#pragma unroll
            for (int nt = 0; nt < 16; nt++) mma_bf16(sacc[nt], qh[kc], kb[nt]);
#pragma unroll
            for (int nt = 0; nt < 16; nt++) mma_bf16(sacc[nt], ql[kc], kb[nt]);
#pragma unroll
            for (int p = 0; p < 8; p++) ldsm4(&kb[2 * p][0], addrK + TILEB + p * (16 * ROWB) + kc * 32);
#pragma unroll
            for (int nt = 0; nt < 16; nt++) mma_bf16(sacc[nt], qh[kc], kb[nt]);
        }

        // ---- softmax epilogue (no max, no rescale): P = exp(S/8), in-register ----
        uint32_t pa[8][4];
#pragma unroll
        for (int nt = 0; nt < 16; nt++) {
            const float p0 = __expf(sacc[nt][0] * 0.125f);
            const float p1 = __expf(sacc[nt][1] * 0.125f);
            const float p2 = __expf(sacc[nt][2] * 0.125f);
            const float p3 = __expf(sacc[nt][3] * 0.125f);
            l0 += p0 + p1;
            l1 += p2 + p3;
            pa[nt >> 1][(nt & 1) * 2 + 0] = pack_bf16x2(p0, p1);
            pa[nt >> 1][(nt & 1) * 2 + 1] = pack_bf16x2(p2, p3);
        }

        // ---- GEMM2: O(16x64 per warp) += P * (Vhi + Vlo) ----
        const uint32_t addrV = cb + 2 * TILEB + lr * ROWB + lc * 2;
#pragma unroll
        for (int ks = 0; ks < 8; ks++) {
            uint32_t vb[8][2];
#pragma unroll
            for (int p = 0; p < 4; p++) ldsm4t(&vb[2 * p][0], addrV + ks * (16 * ROWB) + p * 32);
#pragma unroll
            for (int nt = 0; nt < 8; nt++) mma_bf16(Oacc[nt], pa[ks], vb[nt]);
#pragma unroll
            for (int p = 0; p < 4; p++) ldsm4t(&vb[2 * p][0], addrV + TILEB + ks * (16 * ROWB) + p * 32);
#pragma unroll
            for (int nt = 0; nt < 8; nt++) mma_bf16(Oacc[nt], pa[ks], vb[nt]);
        }
    }

    // ---- writeback: O partials + row-sum partials ----
    const int g  = lid >> 2;
    const int i2 = lid & 3;
    const int r0 = 16 * wid + g;
    const int r1 = r0 + 8;
#pragma unroll
    for (int nt = 0; nt < 8; nt++) {
        const int e = 8 * nt + 2 * i2;
        *(float2*)&g_O[blockIdx.x][r0][e] = make_float2(Oacc[nt][0], Oacc[nt][1]);
        *(float2*)&g_O[blockIdx.x][r1][e] = make_float2(Oacc[nt][2], Oacc[nt][3]);
    }
    l0 += __shfl_xor_sync(0xFFFFFFFF, l0, 1);
    l0 += __shfl_xor_sync(0xFFFFFFFF, l0, 2);
    l1 += __shfl_xor_sync(0xFFFFFFFF, l1, 1);
    l1 += __shfl_xor_sync(0xFFFFFFFF, l1, 2);
    if (i2 == 0) {
        g_l[blockIdx.x][r0] = l0;
        g_l[blockIdx.x][r1] = l1;
    }
}

// ---------------- kernel 4: combine split-K partials, column-reduce ----------------
__global__ void combine_kernel() {
    __shared__ float pool[EDIM];
    const int rb = blockIdx.x;        // 0..63
    const int tid = threadIdx.x;      // 256
    const int e = tid & 63;
    const int rg = tid >> 6;          // 0..3
    if (tid < EDIM) pool[tid] = 0.f;
    __syncthreads();

    float acc = 0.f;
    for (int jj = 0; jj < 32; jj++) {
        const int row = rg * 32 + jj;
        const float la = g_l[2 * rb][row], lb = g_l[2 * rb + 1][row];
        const float inv = 1.f / (la + lb);
        acc += (g_O[2 * rb][row][e] + g_O[2 * rb + 1][row][e]) * inv;
    }
    atomicAdd(&pool[e], acc);
    __syncthreads();
    if (tid < EDIM) g_pool[rb][tid] = pool[tid];
}

// ---------------- kernel 5: final reduce + output projection ----------------
__global__ void final_kernel(const float* __restrict__ Wp,
                             const float* __restrict__ bp,
                             float* __restrict__ out) {
    __shared__ float ps[EDIM];
    __shared__ float cf;
    const int t = threadIdx.x;  // 64 threads

    if (t == 0) {
        float s = 0.f;
        for (int c = 0; c < CONV_BLOCKS; c++) s += g_sig[c];
        cf = s / (float)(CONV_H2 * CONV_W2);
    }
    float pe = 0.f;
    for (int c = 0; c < NRB; c++) pe += g_pool[c][t];
    __syncthreads();
    ps[t] = pe * (1.f / (float)S_LEN) * cf;
    __syncthreads();
    if (t < 4) {
        float o = bp[t];
#pragma unroll 8
        for (int e = 0; e < EDIM; e++) o += ps[e] * Wp[e * 4 + t];
        out[t] = o;
    }
}

// ---------------- launcher ----------------
extern "C" void kernel_launch(void* const* d_in, const int* in_sizes, int n_in,
                              void* d_out, int out_size) {
    const float* x      = (const float*)d_in[0];
    const float* conv_w = (const float*)d_in[1];
    const float* conv_b = (const float*)d_in[2];
    const float* Wq     = (const float*)d_in[3];
    const float* bq     = (const float*)d_in[4];
    const float* Wk     = (const float*)d_in[5];
    const float* bk     = (const float*)d_in[6];
    const float* Wv     = (const float*)d_in[7];
    const float* bv     = (const float*)d_in[8];
    const float* Wp     = (const float*)d_in[9];
    const float* bp     = (const float*)d_in[10];
    float* out = (float*)d_out;

    cudaFuncSetAttribute(fa_kernel, cudaFuncAttributeMaxDynamicSharedMemorySize, SMEM_TOTAL);

    proj_kernel<<<dim3(S_LEN / 32, 3), 256>>>(x, Wq, bq, Wk, bk, Wv, bv);
    conv_kernel<<<CONV_BLOCKS, 256>>>(x, conv_w, conv_b);
    fa_kernel<<<NCTA, 256, SMEM_TOTAL>>>();
    combine_kernel<<<NRB, 256>>>();
    final_kernel<<<1, 64>>>(Wp, bp, out);
}

// round 4
// speedup vs baseline: 8.8355x; 2.6317x over previous
#include <cuda_runtime.h>
#include <cuda_bf16.h>
#include <cstdint>

#define S_LEN 8192
#define EDIM  64
#define BM    128
#define BN    128
#define NRB   (S_LEN / BM)      // 64 row blocks
#define NCTA  (NRB * 2)         // 128 CTAs (x2 key halves)
#define KHALF (S_LEN / 2)       // 4096
#define NTILE (KHALF / BN)      // 32 key tiles per CTA
#define CONV_BLOCKS 256
#define CONV_W2 (S_LEN - 1)
#define CONV_H2 (EDIM - 1)

#define ROWB  144               // padded row stride bytes (64 bf16 + 8 pad)
#define TILEB (128 * ROWB)      // 18432 B per tile buffer
#define SMEM_TOTAL (4 * TILEB)  // 73728 B (double-buffered K,V)

// ---------------- device scratch ----------------
__device__ __nv_bfloat16 g_q[S_LEN * EDIM];
__device__ __nv_bfloat16 g_k[S_LEN * EDIM];
__device__ __nv_bfloat16 g_v[S_LEN * EDIM];
__device__ float g_O[NCTA][BM][EDIM];
__device__ float g_l[NCTA][BM];
__device__ float g_pool[NRB * 8][EDIM];
__device__ float g_sig[CONV_BLOCKS];

// ---------------- PTX helpers (generic sm_80+ features only) ----------------
__device__ __forceinline__ uint32_t smem_u32(const void* p) {
    uint32_t a;
    asm("{ .reg .u64 t; cvta.to.shared.u64 t, %1; cvt.u32.u64 %0, t; }" : "=r"(a) : "l"(p));
    return a;
}
__device__ __forceinline__ void cp16(uint32_t dst, const void* src) {
    asm volatile("cp.async.cg.shared.global [%0], [%1], 16;" :: "r"(dst), "l"(src));
}
#define CP_COMMIT() asm volatile("cp.async.commit_group;" ::: "memory")
#define CP_WAIT0()  asm volatile("cp.async.wait_group 0;" ::: "memory")

__device__ __forceinline__ void ldsm4(uint32_t* r, uint32_t a) {
    asm volatile("ldmatrix.sync.aligned.m8n8.x4.shared.b16 {%0,%1,%2,%3}, [%4];"
                 : "=r"(r[0]), "=r"(r[1]), "=r"(r[2]), "=r"(r[3]) : "r"(a));
}
__device__ __forceinline__ void ldsm4t(uint32_t* r, uint32_t a) {
    asm volatile("ldmatrix.sync.aligned.m8n8.x4.trans.shared.b16 {%0,%1,%2,%3}, [%4];"
                 : "=r"(r[0]), "=r"(r[1]), "=r"(r[2]), "=r"(r[3]) : "r"(a));
}
__device__ __forceinline__ void mma_bf16(float* d, const uint32_t* a, const uint32_t* b) {
    asm volatile("mma.sync.aligned.m16n8k16.row.col.f32.bf16.bf16.f32 "
                 "{%0,%1,%2,%3}, {%4,%5,%6,%7}, {%8,%9}, {%0,%1,%2,%3};"
                 : "+f"(d[0]), "+f"(d[1]), "+f"(d[2]), "+f"(d[3])
                 : "r"(a[0]), "r"(a[1]), "r"(a[2]), "r"(a[3]), "r"(b[0]), "r"(b[1]));
}
__device__ __forceinline__ uint32_t pack_bf16x2(float lo, float hi) {
    uint32_t r;
    asm("cvt.rn.satfinite.bf16x2.f32 %0, %1, %2;" : "=r"(r) : "f"(hi), "f"(lo));
    return r;
}

// ---------------- kernel 1: fused Q/K/V projection (+conv in y==3) ----------------
__global__ void projconv_kernel(const float* __restrict__ x,
                                const float* __restrict__ Wq, const float* __restrict__ bq,
                                const float* __restrict__ Wk, const float* __restrict__ bk,
                                const float* __restrict__ Wv, const float* __restrict__ bv,
                                const float* __restrict__ cw, const float* __restrict__ cb) {
    const int which = blockIdx.y;
    const int tid = threadIdx.x;

    if (which == 3) {
        // ---- conv 2x2 + sigmoid partial sums ----
        const float w00 = cw[0], w01 = cw[1], w10 = cw[2], w11 = cw[3];
        const float bias = cb[0];
        const int total = CONV_H2 * CONV_W2;

        float acc = 0.f;
        for (int n = blockIdx.x * 256 + tid; n < total; n += CONV_BLOCKS * 256) {
            const int i = n % CONV_H2;
            const int j = n / CONV_H2;
            const float z = w00 * x[j * EDIM + i]
                          + w01 * x[(j + 1) * EDIM + i]
                          + w10 * x[j * EDIM + i + 1]
                          + w11 * x[(j + 1) * EDIM + i + 1]
                          + bias;
            acc += 1.f / (1.f + __expf(-z));
        }
        __shared__ float red[256];
        red[tid] = acc;
        __syncthreads();
        for (int s2 = 128; s2 > 0; s2 >>= 1) {
            if (tid < s2) red[tid] += red[tid + s2];
            __syncthreads();
        }
        if (tid == 0) g_sig[blockIdx.x] = red[0];
        return;
    }

    __shared__ float xs[32][EDIM];
    __shared__ float Ws[EDIM][EDIM];
    __shared__ float bs[EDIM];

    const float* W = (which == 0) ? Wq : (which == 1) ? Wk : Wv;
    const float* b = (which == 0) ? bq : (which == 1) ? bk : bv;
    __nv_bfloat16* dst = (which == 0) ? g_q : (which == 1) ? g_k : g_v;

    const int r0 = blockIdx.x * 32;

    for (int i = tid; i < 32 * EDIM; i += 256)
        xs[i >> 6][i & 63] = x[(r0 + (i >> 6)) * EDIM + (i & 63)];
    for (int i = tid; i < EDIM * EDIM; i += 256)
        Ws[i >> 6][i & 63] = W[i];
    if (tid < EDIM) bs[tid] = b[tid];
    __syncthreads();

    const int e  = tid & 63;
    const int rg = tid >> 6;     // 0..3
    float acc[8];
#pragma unroll
    for (int k = 0; k < 8; k++) acc[k] = bs[e];
#pragma unroll 8
    for (int f = 0; f < EDIM; f++) {
        const float w = Ws[f][e];
#pragma unroll
        for (int k = 0; k < 8; k++) acc[k] += xs[rg + 4 * k][f] * w;
    }
#pragma unroll
    for (int k = 0; k < 8; k++)
        dst[(r0 + rg + 4 * k) * EDIM + e] = __float2bfloat16(acc[k]);
}

// ---------------- async tile loader: 128 rows x 64 bf16, padded rows ----------------
__device__ __forceinline__ void load_part(uint32_t dst, const __nv_bfloat16* __restrict__ src,
                                          int row0, int tid) {
#pragma unroll
    for (int it = 0; it < 4; it++) {
        const int n = tid + it * 256;
        const int j = n >> 3, seg = n & 7;
        cp16(dst + j * ROWB + seg * 16, src + (row0 + j) * EDIM + seg * 8);
    }
}

// ---------------- kernel 2: HMMA flash attention (no-max softmax, split-K) ----------------
__global__ void __launch_bounds__(256, 1) fa_kernel() {
    extern __shared__ char sm[];
    const uint32_t smb = smem_u32(sm);
    const int tid = threadIdx.x;
    const int wid = tid >> 5;
    const int lid = tid & 31;
    const int rb = blockIdx.x >> 1;
    const int kh = blockIdx.x & 1;
    const int i0 = rb * BM;
    const int kbase = kh * KHALF;

    // lane offset patterns for ldmatrix address generation
    const int lr  = (lid & 7) + ((lid >> 3) & 1) * 8;   // A / V(trans) row pattern
    const int lc  = ((lid >> 4) & 1) * 8;               // A / V(trans) col pattern
    const int lr2 = (lid & 7) + ((lid >> 4) & 1) * 8;   // K(B) row pattern
    const int lc2 = ((lid >> 3) & 1) * 8;               // K(B) col pattern

    // ---- stage Q through smem, build persistent A-frags ----
#pragma unroll
    for (int it = 0; it < 4; it++) {
        const int n = tid + it * 256;
        const int j = n >> 3, seg = n & 7;
        *(uint4*)(sm + j * ROWB + seg * 16) = *(const uint4*)(g_q + (i0 + j) * EDIM + seg * 8);
    }
    __syncthreads();

    uint32_t qh[4][4];
    {
        const uint32_t addrA = smb + (16 * wid + lr) * ROWB + lc * 2;
#pragma unroll
        for (int kc = 0; kc < 4; kc++) ldsm4(qh[kc], addrA + kc * 32);
    }
    __syncthreads();

    // ---- prologue: prefetch tile 0 into buffer 0 ----
    load_part(smb + 0 * TILEB, g_k, kbase, tid);
    load_part(smb + 1 * TILEB, g_v, kbase, tid);
    CP_COMMIT();

    float Oacc[8][4];
#pragma unroll
    for (int i = 0; i < 8; i++)
#pragma unroll
        for (int j = 0; j < 4; j++) Oacc[i][j] = 0.f;
    float l0 = 0.f, l1 = 0.f;

    for (int t = 0; t < NTILE; t++) {
        CP_WAIT0();
        __syncthreads();

        if (t + 1 < NTILE) {  // prefetch next tile into other buffer
            const uint32_t nb = smb + ((t + 1) & 1) * 2 * TILEB;
            const int k0n = kbase + (t + 1) * BN;
            load_part(nb + 0 * TILEB, g_k, k0n, tid);
            load_part(nb + 1 * TILEB, g_v, k0n, tid);
            CP_COMMIT();
        }

        const uint32_t cb = smb + (t & 1) * 2 * TILEB;

        // ---- GEMM1: S(16x128 per warp) = Q * K^T (single bf16 pass) ----
        float sacc[16][4];
#pragma unroll
        for (int i = 0; i < 16; i++)
#pragma unroll
            for (int j = 0; j < 4; j++) sacc[i][j] = 0.f;

        const uint32_t addrK = cb + lr2 * ROWB + lc2 * 2;
#pragma unroll
        for (int kc = 0; kc < 4; kc++) {
            uint32_t kb[16][2];
#pragma unroll
            for (int p = 0; p < 8; p++) ldsm4(&kb[2 * p][0], addrK + p * (16 * ROWB) + kc * 32);
#pragma unroll
            for (int nt = 0; nt < 16; nt++) mma_bf16(sacc[nt], qh[kc], kb[nt]);
        }

        // ---- softmax epilogue (no max, no rescale): P = exp(S/8), in-register ----
        uint32_t pa[8][4];
#pragma unroll
        for (int nt = 0; nt < 16; nt++) {
            const float p0 = __expf(sacc[nt][0] * 0.125f);
            const float p1 = __expf(sacc[nt][1] * 0.125f);
            const float p2 = __expf(sacc[nt][2] * 0.125f);
            const float p3 = __expf(sacc[nt][3] * 0.125f);
            l0 += p0 + p1;
            l1 += p2 + p3;
            pa[nt >> 1][(nt & 1) * 2 + 0] = pack_bf16x2(p0, p1);
            pa[nt >> 1][(nt & 1) * 2 + 1] = pack_bf16x2(p2, p3);
        }

        // ---- GEMM2: O(16x64 per warp) += P * V (single bf16 pass) ----
        const uint32_t addrV = cb + TILEB + lr * ROWB + lc * 2;
#pragma unroll
        for (int ks = 0; ks < 8; ks++) {
            uint32_t vb[8][2];
#pragma unroll
            for (int p = 0; p < 4; p++) ldsm4t(&vb[2 * p][0], addrV + ks * (16 * ROWB) + p * 32);
#pragma unroll
            for (int nt = 0; nt < 8; nt++) mma_bf16(Oacc[nt], pa[ks], vb[nt]);
        }
    }

    // ---- writeback: O partials + row-sum partials ----
    const int g  = lid >> 2;
    const int i2 = lid & 3;
    const int r0 = 16 * wid + g;
    const int r1 = r0 + 8;
#pragma unroll
    for (int nt = 0; nt < 8; nt++) {
        const int e = 8 * nt + 2 * i2;
        *(float2*)&g_O[blockIdx.x][r0][e] = make_float2(Oacc[nt][0], Oacc[nt][1]);
        *(float2*)&g_O[blockIdx.x][r1][e] = make_float2(Oacc[nt][2], Oacc[nt][3]);
    }
    l0 += __shfl_xor_sync(0xFFFFFFFF, l0, 1);
    l0 += __shfl_xor_sync(0xFFFFFFFF, l0, 2);
    l1 += __shfl_xor_sync(0xFFFFFFFF, l1, 1);
    l1 += __shfl_xor_sync(0xFFFFFFFF, l1, 2);
    if (i2 == 0) {
        g_l[blockIdx.x][r0] = l0;
        g_l[blockIdx.x][r1] = l1;
    }
}

// ---------------- kernel 3: combine split-K partials, column-reduce ----------------
__global__ void combine_kernel() {
    __shared__ float pool[EDIM];
    const int rb  = blockIdx.x;       // 0..63
    const int grp = blockIdx.y;       // 0..7 (16 rows each)
    const int tid = threadIdx.x;      // 256
    const int e = tid & 63;
    const int rg = tid >> 6;          // 0..3
    if (tid < EDIM) pool[tid] = 0.f;
    __syncthreads();

    float acc = 0.f;
#pragma unroll
    for (int jj = 0; jj < 4; jj++) {
        const int row = grp * 16 + rg * 4 + jj;
        const float la = g_l[2 * rb][row], lb = g_l[2 * rb + 1][row];
        const float inv = 1.f / (la + lb);
        acc += (g_O[2 * rb][row][e] + g_O[2 * rb + 1][row][e]) * inv;
    }
    atomicAdd(&pool[e], acc);
    __syncthreads();
    if (tid < EDIM) g_pool[rb * 8 + grp][tid] = pool[tid];
}

// ---------------- kernel 4: final reduce + output projection ----------------
__global__ void final_kernel(const float* __restrict__ Wp,
                             const float* __restrict__ bp,
                             float* __restrict__ out) {
    __shared__ float red[256];
    __shared__ float ps[EDIM];
    const int t = threadIdx.x;  // 256

    red[t] = g_sig[t];
    __syncthreads();
    for (int s2 = 128; s2 > 0; s2 >>= 1) {
        if (t < s2) red[t] += red[t + s2];
        __syncthreads();
    }

    const int e = t & 63;
    const int q = t >> 6;       // 0..3
    float pe = 0.f;
#pragma unroll 8
    for (int c = 0; c < 128; c++) pe += g_pool[q * 128 + c][e];
    if (t < EDIM) ps[t] = 0.f;
    __syncthreads();
    atomicAdd(&ps[e], pe);
    __syncthreads();

    if (t < 4) {
        const float cf = red[0] / (float)(CONV_H2 * CONV_W2);
        float o = bp[t];
#pragma unroll 8
        for (int k = 0; k < EDIM; k++)
            o += ps[k] * (1.f / (float)S_LEN) * cf * Wp[k * 4 + t];
        out[t] = o;
    }
}

// ---------------- launcher ----------------
extern "C" void kernel_launch(void* const* d_in, const int* in_sizes, int n_in,
                              void* d_out, int out_size) {
    const float* x      = (const float*)d_in[0];
    const float* conv_w = (const float*)d_in[1];
    const float* conv_b = (const float*)d_in[2];
    const float* Wq     = (const float*)d_in[3];
    const float* bq     = (const float*)d_in[4];
    const float* Wk     = (const float*)d_in[5];
    const float* bk     = (const float*)d_in[6];
    const float* Wv     = (const float*)d_in[7];
    const float* bv     = (const float*)d_in[8];
    const float* Wp     = (const float*)d_in[9];
    const float* bp     = (const float*)d_in[10];
    float* out = (float*)d_out;

    cudaFuncSetAttribute(fa_kernel, cudaFuncAttributeMaxDynamicSharedMemorySize, SMEM_TOTAL);

    projconv_kernel<<<dim3(CONV_BLOCKS, 4), 256>>>(x, Wq, bq, Wk, bk, Wv, bv, conv_w, conv_b);
    fa_kernel<<<NCTA, 256, SMEM_TOTAL>>>();
    combine_kernel<<<dim3(NRB, 8), 256>>>();
    final_kernel<<<1, 256>>>(Wp, bp, out);
}

// round 5
// speedup vs baseline: 9.2770x; 1.0500x over previous
#include <cuda_runtime.h>
#include <cuda_bf16.h>
#include <cstdint>

#define S_LEN 8192
#define EDIM  64
#define BM    128
#define BN    128
#define NRB   (S_LEN / BM)      // 64 row blocks
#define NCTA  (NRB * 2)         // 128 CTAs (x2 key halves)
#define KHALF (S_LEN / 2)       // 4096
#define NTILE (KHALF / BN)      // 32 key tiles per CTA
#define CONV_BLOCKS 256
#define CONV_W2 (S_LEN - 1)
#define CONV_H2 (EDIM - 1)

#define ROWB  144               // padded row stride bytes (64 bf16 + 8 pad)
#define TILEB (128 * ROWB)      // 18432 B per tile buffer
#define SMEM_TOTAL (4 * TILEB)  // 73728 B (double-buffered K,V)

// ---------------- device scratch ----------------
__device__ __nv_bfloat16 g_q[S_LEN * EDIM];
__device__ __nv_bfloat16 g_k[S_LEN * EDIM];
__device__ __nv_bfloat16 g_v[S_LEN * EDIM];
__device__ float g_O[NCTA][BM][EDIM];
__device__ float g_l[NCTA][BM];
__device__ float g_final[EDIM];
__device__ float g_sig[CONV_BLOCKS];

// ---------------- PTX helpers (generic sm_80+ features only) ----------------
__device__ __forceinline__ uint32_t smem_u32(const void* p) {
    uint32_t a;
    asm("{ .reg .u64 t; cvta.to.shared.u64 t, %1; cvt.u32.u64 %0, t; }" : "=r"(a) : "l"(p));
    return a;
}
__device__ __forceinline__ void cp16(uint32_t dst, const void* src) {
    asm volatile("cp.async.cg.shared.global [%0], [%1], 16;" :: "r"(dst), "l"(src));
}
#define CP_COMMIT() asm volatile("cp.async.commit_group;" ::: "memory")
#define CP_WAIT0()  asm volatile("cp.async.wait_group 0;" ::: "memory")

__device__ __forceinline__ void ldsm4(uint32_t* r, uint32_t a) {
    asm volatile("ldmatrix.sync.aligned.m8n8.x4.shared.b16 {%0,%1,%2,%3}, [%4];"
                 : "=r"(r[0]), "=r"(r[1]), "=r"(r[2]), "=r"(r[3]) : "r"(a));
}
__device__ __forceinline__ void ldsm4t(uint32_t* r, uint32_t a) {
    asm volatile("ldmatrix.sync.aligned.m8n8.x4.trans.shared.b16 {%0,%1,%2,%3}, [%4];"
                 : "=r"(r[0]), "=r"(r[1]), "=r"(r[2]), "=r"(r[3]) : "r"(a));
}
__device__ __forceinline__ void mma_bf16(float* d, const uint32_t* a, const uint32_t* b) {
    asm volatile("mma.sync.aligned.m16n8k16.row.col.f32.bf16.bf16.f32 "
                 "{%0,%1,%2,%3}, {%4,%5,%6,%7}, {%8,%9}, {%0,%1,%2,%3};"
                 : "+f"(d[0]), "+f"(d[1]), "+f"(d[2]), "+f"(d[3])
                 : "r"(a[0]), "r"(a[1]), "r"(a[2]), "r"(a[3]), "r"(b[0]), "r"(b[1]));
}
__device__ __forceinline__ uint32_t pack_bf16x2(float lo, float hi) {
    uint32_t r;
    asm("cvt.rn.satfinite.bf16x2.f32 %0, %1, %2;" : "=r"(r) : "f"(hi), "f"(lo));
    return r;
}

// ---------------- kernel 1: fused Q/K/V projection (+conv in y==3, zeroing) ----------------
__global__ void projconv_kernel(const float* __restrict__ x,
                                const float* __restrict__ Wq, const float* __restrict__ bq,
                                const float* __restrict__ Wk, const float* __restrict__ bk,
                                const float* __restrict__ Wv, const float* __restrict__ bv,
                                const float* __restrict__ cw, const float* __restrict__ cb) {
    const int which = blockIdx.y;
    const int tid = threadIdx.x;

    if (which == 3) {
        // zero the global accumulator (used by combine_kernel later in the stream)
        if (blockIdx.x == 0 && tid < EDIM) g_final[tid] = 0.f;

        // ---- conv 2x2 + sigmoid partial sums ----
        const float w00 = cw[0], w01 = cw[1], w10 = cw[2], w11 = cw[3];
        const float bias = cb[0];
        const int total = CONV_H2 * CONV_W2;

        float acc = 0.f;
        for (int n = blockIdx.x * 256 + tid; n < total; n += CONV_BLOCKS * 256) {
            const int i = n % CONV_H2;
            const int j = n / CONV_H2;
            const float z = w00 * x[j * EDIM + i]
                          + w01 * x[(j + 1) * EDIM + i]
                          + w10 * x[j * EDIM + i + 1]
                          + w11 * x[(j + 1) * EDIM + i + 1]
                          + bias;
            acc += 1.f / (1.f + __expf(-z));
        }
        __shared__ float red[256];
        red[tid] = acc;
        __syncthreads();
        for (int s2 = 128; s2 > 0; s2 >>= 1) {
            if (tid < s2) red[tid] += red[tid + s2];
            __syncthreads();
        }
        if (tid == 0) g_sig[blockIdx.x] = red[0];
        return;
    }

    __shared__ float xs[32][EDIM];
    __shared__ float Ws[EDIM][EDIM];
    __shared__ float bs[EDIM];

    const float* W = (which == 0) ? Wq : (which == 1) ? Wk : Wv;
    const float* b = (which == 0) ? bq : (which == 1) ? bk : bv;
    __nv_bfloat16* dst = (which == 0) ? g_q : (which == 1) ? g_k : g_v;

    const int r0 = blockIdx.x * 32;

    for (int i = tid; i < 32 * EDIM; i += 256)
        xs[i >> 6][i & 63] = x[(r0 + (i >> 6)) * EDIM + (i & 63)];
    for (int i = tid; i < EDIM * EDIM; i += 256)
        Ws[i >> 6][i & 63] = W[i];
    if (tid < EDIM) bs[tid] = b[tid];
    __syncthreads();

    const int e  = tid & 63;
    const int rg = tid >> 6;     // 0..3
    float acc[8];
#pragma unroll
    for (int k = 0; k < 8; k++) acc[k] = bs[e];
#pragma unroll 8
    for (int f = 0; f < EDIM; f++) {
        const float w = Ws[f][e];
#pragma unroll
        for (int k = 0; k < 8; k++) acc[k] += xs[rg + 4 * k][f] * w;
    }
#pragma unroll
    for (int k = 0; k < 8; k++)
        dst[(r0 + rg + 4 * k) * EDIM + e] = __float2bfloat16(acc[k]);
}

// ---------------- async tile loader: 128 rows x 64 bf16, padded rows ----------------
__device__ __forceinline__ void load_part(uint32_t dst, const __nv_bfloat16* __restrict__ src,
                                          int row0, int tid) {
#pragma unroll
    for (int it = 0; it < 4; it++) {
        const int n = tid + it * 256;
        const int j = n >> 3, seg = n & 7;
        cp16(dst + j * ROWB + seg * 16, src + (row0 + j) * EDIM + seg * 8);
    }
}

// ---------------- kernel 2: HMMA flash attention (no-max softmax, split-K) ----------------
__global__ void __launch_bounds__(256, 1) fa_kernel() {
    extern __shared__ char sm[];
    const uint32_t smb = smem_u32(sm);
    const int tid = threadIdx.x;
    const int wid = tid >> 5;
    const int lid = tid & 31;
    const int rb = blockIdx.x >> 1;
    const int kh = blockIdx.x & 1;
    const int i0 = rb * BM;
    const int kbase = kh * KHALF;

    // lane offset patterns for ldmatrix address generation
    const int lr  = (lid & 7) + ((lid >> 3) & 1) * 8;   // A / V(trans) row pattern
    const int lc  = ((lid >> 4) & 1) * 8;               // A / V(trans) col pattern
    const int lr2 = (lid & 7) + ((lid >> 4) & 1) * 8;   // K(B) row pattern
    const int lc2 = ((lid >> 3) & 1) * 8;               // K(B) col pattern

    // ---- stage Q through smem, build persistent A-frags ----
#pragma unroll
    for (int it = 0; it < 4; it++) {
        const int n = tid + it * 256;
        const int j = n >> 3, seg = n & 7;
        *(uint4*)(sm + j * ROWB + seg * 16) = *(const uint4*)(g_q + (i0 + j) * EDIM + seg * 8);
    }
    __syncthreads();

    uint32_t qh[4][4];
    {
        const uint32_t addrA = smb + (16 * wid + lr) * ROWB + lc * 2;
#pragma unroll
        for (int kc = 0; kc < 4; kc++) ldsm4(qh[kc], addrA + kc * 32);
    }
    __syncthreads();

    // ---- prologue: prefetch tile 0 into buffer 0 ----
    load_part(smb + 0 * TILEB, g_k, kbase, tid);
    load_part(smb + 1 * TILEB, g_v, kbase, tid);
    CP_COMMIT();

    float Oacc[8][4];
#pragma unroll
    for (int i = 0; i < 8; i++)
#pragma unroll
        for (int j = 0; j < 4; j++) Oacc[i][j] = 0.f;
    float l0 = 0.f, l1 = 0.f;

    for (int t = 0; t < NTILE; t++) {
        CP_WAIT0();
        __syncthreads();

        if (t + 1 < NTILE) {  // prefetch next tile into other buffer
            const uint32_t nb = smb + ((t + 1) & 1) * 2 * TILEB;
            const int k0n = kbase + (t + 1) * BN;
            load_part(nb + 0 * TILEB, g_k, k0n, tid);
            load_part(nb + 1 * TILEB, g_v, k0n, tid);
            CP_COMMIT();
        }

        const uint32_t cb = smb + (t & 1) * 2 * TILEB;

        // ---- GEMM1: S(16x128 per warp) = Q * K^T ----
        float sacc[16][4];
#pragma unroll
        for (int i = 0; i < 16; i++)
#pragma unroll
            for (int j = 0; j < 4; j++) sacc[i][j] = 0.f;

        const uint32_t addrK = cb + lr2 * ROWB + lc2 * 2;
#pragma unroll
        for (int kc = 0; kc < 4; kc++) {
            uint32_t kb[16][2];
#pragma unroll
            for (int p = 0; p < 8; p++) ldsm4(&kb[2 * p][0], addrK + p * (16 * ROWB) + kc * 32);
#pragma unroll
            for (int nt = 0; nt < 16; nt++) mma_bf16(sacc[nt], qh[kc], kb[nt]);
        }

        // ---- softmax epilogue (no max, no rescale): P = exp(S/8), in-register ----
        uint32_t pa[8][4];
#pragma unroll
        for (int nt = 0; nt < 16; nt++) {
            const float p0 = __expf(sacc[nt][0] * 0.125f);
            const float p1 = __expf(sacc[nt][1] * 0.125f);
            const float p2 = __expf(sacc[nt][2] * 0.125f);
            const float p3 = __expf(sacc[nt][3] * 0.125f);
            l0 += p0 + p1;
            l1 += p2 + p3;
            pa[nt >> 1][(nt & 1) * 2 + 0] = pack_bf16x2(p0, p1);
            pa[nt >> 1][(nt & 1) * 2 + 1] = pack_bf16x2(p2, p3);
        }

        // ---- GEMM2: O(16x64 per warp) += P * V ----
        const uint32_t addrV = cb + TILEB + lr * ROWB + lc * 2;
#pragma unroll
        for (int ks = 0; ks < 8; ks++) {
            uint32_t vb[8][2];
#pragma unroll
            for (int p = 0; p < 4; p++) ldsm4t(&vb[2 * p][0], addrV + ks * (16 * ROWB) + p * 32);
#pragma unroll
            for (int nt = 0; nt < 8; nt++) mma_bf16(Oacc[nt], pa[ks], vb[nt]);
        }
    }

    // ---- writeback: O partials + row-sum partials ----
    const int g  = lid >> 2;
    const int i2 = lid & 3;
    const int r0 = 16 * wid + g;
    const int r1 = r0 + 8;
#pragma unroll
    for (int nt = 0; nt < 8; nt++) {
        const int e = 8 * nt + 2 * i2;
        *(float2*)&g_O[blockIdx.x][r0][e] = make_float2(Oacc[nt][0], Oacc[nt][1]);
        *(float2*)&g_O[blockIdx.x][r1][e] = make_float2(Oacc[nt][2], Oacc[nt][3]);
    }
    l0 += __shfl_xor_sync(0xFFFFFFFF, l0, 1);
    l0 += __shfl_xor_sync(0xFFFFFFFF, l0, 2);
    l1 += __shfl_xor_sync(0xFFFFFFFF, l1, 1);
    l1 += __shfl_xor_sync(0xFFFFFFFF, l1, 2);
    if (i2 == 0) {
        g_l[blockIdx.x][r0] = l0;
        g_l[blockIdx.x][r1] = l1;
    }
}

// ---------------- kernel 3: combine split-K partials -> atomic global accumulate ----------------
__global__ void combine_kernel() {
    __shared__ float pool[EDIM];
    const int rb  = blockIdx.x;       // 0..63
    const int grp = blockIdx.y;       // 0..7 (16 rows each)
    const int tid = threadIdx.x;      // 256
    const int e = tid & 63;
    const int rg = tid >> 6;          // 0..3
    if (tid < EDIM) pool[tid] = 0.f;
    __syncthreads();

    float acc = 0.f;
#pragma unroll
    for (int jj = 0; jj < 4; jj++) {
        const int row = grp * 16 + rg * 4 + jj;
        const float la = g_l[2 * rb][row], lb = g_l[2 * rb + 1][row];
        const float inv = 1.f / (la + lb);
        acc += (g_O[2 * rb][row][e] + g_O[2 * rb + 1][row][e]) * inv;
    }
    atomicAdd(&pool[e], acc);
    __syncthreads();
    if (tid < EDIM) atomicAdd(&g_final[tid], pool[tid]);
}

// ---------------- kernel 4: tiny final: sig reduce + output projection ----------------
__global__ void final_kernel(const float* __restrict__ Wp,
                             const float* __restrict__ bp,
                             float* __restrict__ out) {
    __shared__ float red[256];
    __shared__ float ps[EDIM];
    const int t = threadIdx.x;  // 256

    red[t] = g_sig[t];
    if (t < EDIM) ps[t] = g_final[t];
    __syncthreads();
    for (int s2 = 128; s2 > 0; s2 >>= 1) {
        if (t < s2) red[t] += red[t + s2];
        __syncthreads();
    }

    if (t < 4) {
        const float cf = red[0] / (float)(CONV_H2 * CONV_W2);
        const float sc = cf * (1.f / (float)S_LEN);
        float o = bp[t];
#pragma unroll 8
        for (int k = 0; k < EDIM; k++)
            o += ps[k] * sc * Wp[k * 4 + t];
        out[t] = o;
    }
}

// ---------------- launcher ----------------
extern "C" void kernel_launch(void* const* d_in, const int* in_sizes, int n_in,
                              void* d_out, int out_size) {
    const float* x      = (const float*)d_in[0];
    const float* conv_w = (const float*)d_in[1];
    const float* conv_b = (const float*)d_in[2];
    const float* Wq     = (const float*)d_in[3];
    const float* bq     = (const float*)d_in[4];
    const float* Wk     = (const float*)d_in[5];
    const float* bk     = (const float*)d_in[6];
    const float* Wv     = (const float*)d_in[7];
    const float* bv     = (const float*)d_in[8];
    const float* Wp     = (const float*)d_in[9];
    const float* bp     = (const float*)d_in[10];
    float* out = (float*)d_out;

    cudaFuncSetAttribute(fa_kernel, cudaFuncAttributeMaxDynamicSharedMemorySize, SMEM_TOTAL);

    projconv_kernel<<<dim3(CONV_BLOCKS, 4), 256>>>(x, Wq, bq, Wk, bk, Wv, bv, conv_w, conv_b);
    fa_kernel<<<NCTA, 256, SMEM_TOTAL>>>();
    combine_kernel<<<dim3(NRB, 8), 256>>>();
    final_kernel<<<1, 256>>>(Wp, bp, out);
}